// round 5
// baseline (speedup 1.0000x reference)
#include <cuda_runtime.h>

// Gray-Scott reaction-diffusion residual, y-march (chunked), float2,
// single-pointer immediate-offset addressing.
// Input:  output [50, 2, 100, 100, 100] fp32  (d_in[0])
// Output: f_u (48,96,96,96) then f_v (48,96,96,96), fp32.

#define SLICE_C  1000000      // 100^3 floats (u->v channel offset)
#define STRIDE_T 2000000      // floats per timestep (2 channels)
#define PLANE    10000        // 100*100
#define ROW      100
#define OUTE     96
#define OUTP     (96*96)      // 9216
#define OUTVOL   (96*96*96)   // 884736
#define YCHUNK   24           // y steps per block

#define LD2(p, off) (*(const float2*)((p) + (off)))

__global__ void __launch_bounds__(192, 7) gs_residual_v5(
    const float* __restrict__ in, float* __restrict__ out)
{
    const int zp = threadIdx.x;                    // 0..47 (z pair)
    const int z  = zp * 2;                         // output z (even)
    const int x  = blockIdx.x * 4 + threadIdx.y;   // 0..95
    const int yb = blockIdx.y * YCHUNK;            // output y chunk start
    const int t  = blockIdx.z;                     // 0..47

    // p points at the float2 center column in plane (yb + yy), channel u, time t.
    const float* p = in + (long long)t * STRIDE_T
                        + (long long)yb * PLANE
                        + (x + 2) * ROW + (z + 2);

    const float S0 = -1.0f / 12.0f;
    const float S1 = 4.0f / 3.0f;
    const float SC = -7.5f;
    const float DXv = 100.0f / 48.0f;
    const float INV_DX2 = 1.0f / (DXv * DXv);
    const float INV_DT = 2.0f;               // 1/0.5
    const float DU = 0.2f, DV = 0.1f, FF = 0.025f, KK = 0.055f;

    // register queue of center float2s for input planes yb .. yb+3
    float2 qu[5], qv[5];
#pragma unroll
    for (int i = 0; i < 4; i++) {
        qu[i] = LD2(p, i * PLANE);
        qv[i] = LD2(p, i * PLANE + SLICE_C);
    }

    float* ou = out + t * OUTVOL + yb * OUTP + x * OUTE + z;
    float* ov = ou + 48 * OUTVOL;

#pragma unroll 2
    for (int yy = 0; yy < YCHUNK; yy++) {
        // center plane is p + 2*PLANE; far plane (y+4) is p + 4*PLANE
        qu[4] = LD2(p, 4 * PLANE);
        qv[4] = LD2(p, 4 * PLANE + SLICE_C);

        // z-halo: left = inputs z, z+1 ; right = inputs z+4, z+5
        float2 uzl = LD2(p, 2 * PLANE - 2);
        float2 uzr = LD2(p, 2 * PLANE + 2);
        float2 vzl = LD2(p, 2 * PLANE - 2 + SLICE_C);
        float2 vzr = LD2(p, 2 * PLANE + 2 + SLICE_C);

        // x taps
        float2 uxm1 = LD2(p, 2 * PLANE - ROW);
        float2 uxp1 = LD2(p, 2 * PLANE + ROW);
        float2 uxm2 = LD2(p, 2 * PLANE - 2 * ROW);
        float2 uxp2 = LD2(p, 2 * PLANE + 2 * ROW);
        float2 vxm1 = LD2(p, 2 * PLANE - ROW + SLICE_C);
        float2 vxp1 = LD2(p, 2 * PLANE + ROW + SLICE_C);
        float2 vxm2 = LD2(p, 2 * PLANE - 2 * ROW + SLICE_C);
        float2 vxp2 = LD2(p, 2 * PLANE + 2 * ROW + SLICE_C);

        // t+1 centers
        float2 unx = LD2(p, 2 * PLANE + STRIDE_T);
        float2 vnx = LD2(p, 2 * PLANE + STRIDE_T + SLICE_C);

        float2 uc = qu[2];
        float2 vc = qv[2];

        // ---- u laplacian ----
        // point 0 (input z+2): z±1 = uzl.y, uc.y ; z±2 = uzl.x, uzr.x
        float s1u0 = uzl.y + uc.y + uxm1.x + uxp1.x + qu[1].x + qu[3].x;
        float s2u0 = uzl.x + uzr.x + uxm2.x + uxp2.x + qu[0].x + qu[4].x;
        // point 1 (input z+3): z±1 = uc.x, uzr.x ; z±2 = uzl.y, uzr.y
        float s1u1 = uc.x + uzr.x + uxm1.y + uxp1.y + qu[1].y + qu[3].y;
        float s2u1 = uzl.y + uzr.y + uxm2.y + uxp2.y + qu[0].y + qu[4].y;
        float lapu0 = (S1 * s1u0 + S0 * s2u0 + SC * uc.x) * INV_DX2;
        float lapu1 = (S1 * s1u1 + S0 * s2u1 + SC * uc.y) * INV_DX2;

        // ---- v laplacian ----
        float s1v0 = vzl.y + vc.y + vxm1.x + vxp1.x + qv[1].x + qv[3].x;
        float s2v0 = vzl.x + vzr.x + vxm2.x + vxp2.x + qv[0].x + qv[4].x;
        float s1v1 = vc.x + vzr.x + vxm1.y + vxp1.y + qv[1].y + qv[3].y;
        float s2v1 = vzl.y + vzr.y + vxm2.y + vxp2.y + qv[0].y + qv[4].y;
        float lapv0 = (S1 * s1v0 + S0 * s2v0 + SC * vc.x) * INV_DX2;
        float lapv1 = (S1 * s1v1 + S0 * s2v1 + SC * vc.y) * INV_DX2;

        // ---- reaction + time derivative ----
        float uvv0 = uc.x * vc.x * vc.x;
        float uvv1 = uc.y * vc.y * vc.y;
        float ut0 = (unx.x - uc.x) * INV_DT;
        float ut1 = (unx.y - uc.y) * INV_DT;
        float vt0 = (vnx.x - vc.x) * INV_DT;
        float vt1 = (vnx.y - vc.y) * INV_DT;

        float2 fu, fv;
        fu.x = DU * lapu0 - uvv0 + FF * (1.0f - uc.x) - ut0;
        fu.y = DU * lapu1 - uvv1 + FF * (1.0f - uc.y) - ut1;
        fv.x = DV * lapv0 + uvv0 - (FF + KK) * vc.x - vt0;
        fv.y = DV * lapv1 + uvv1 - (FF + KK) * vc.y - vt1;

        *(float2*)ou = fu;
        *(float2*)ov = fv;
        ou += OUTP;
        ov += OUTP;
        p  += PLANE;

        // shift queues
        qu[0] = qu[1]; qu[1] = qu[2]; qu[2] = qu[3]; qu[3] = qu[4];
        qv[0] = qv[1]; qv[1] = qv[2]; qv[2] = qv[3]; qv[3] = qv[4];
    }
}

extern "C" void kernel_launch(void* const* d_in, const int* in_sizes, int n_in,
                              void* d_out, int out_size)
{
    const float* in = (const float*)d_in[0];
    float* out = (float*)d_out;
    dim3 grid(24, 4, 48);    // x-tiles (96/4), y-chunks, t
    dim3 block(48, 4);       // z-pairs, x within tile
    gs_residual_v5<<<grid, block>>>(in, out);
}

// round 6
// speedup vs baseline: 1.0872x; 1.0872x over previous
#include <cuda_runtime.h>

// Gray-Scott reaction-diffusion residual, y-march (chunked), float2,
// single-pointer immediate-offset addressing, loads front-batched.
// Input:  output [50, 2, 100, 100, 100] fp32  (d_in[0])
// Output: f_u (48,96,96,96) then f_v (48,96,96,96), fp32.

#define SLICE_C  1000000      // 100^3 floats (u->v channel offset)
#define STRIDE_T 2000000      // floats per timestep (2 channels)
#define PLANE    10000        // 100*100
#define ROW      100
#define OUTE     96
#define OUTP     (96*96)      // 9216
#define OUTVOL   (96*96*96)   // 884736
#define YCHUNK   24           // y steps per block

#define LD2(p, off) (*(const float2*)((p) + (off)))

__global__ void __launch_bounds__(192, 6) gs_residual_v6(
    const float* __restrict__ in, float* __restrict__ out)
{
    const int zp = threadIdx.x;                    // 0..47 (z pair)
    const int z  = zp * 2;                         // output z (even)
    const int x  = blockIdx.x * 4 + threadIdx.y;   // 0..95
    const int yb = blockIdx.y * YCHUNK;            // output y chunk start
    const int t  = blockIdx.z;                     // 0..47

    // p points at the float2 center column in plane (yb + yy), channel u, time t.
    const float* p = in + (long long)t * STRIDE_T
                        + (long long)yb * PLANE
                        + (x + 2) * ROW + (z + 2);

    const float S0 = -1.0f / 12.0f;
    const float S1 = 4.0f / 3.0f;
    const float SC = -7.5f;
    const float DXv = 100.0f / 48.0f;
    const float INV_DX2 = 1.0f / (DXv * DXv);
    const float INV_DT = 2.0f;               // 1/0.5
    const float DU = 0.2f, DV = 0.1f, FF = 0.025f, KK = 0.055f;

    // register queue of center float2s for input planes yb .. yb+3
    float2 qu[5], qv[5];
#pragma unroll
    for (int i = 0; i < 4; i++) {
        qu[i] = LD2(p, i * PLANE);
        qv[i] = LD2(p, i * PLANE + SLICE_C);
    }

    float* ou = out + t * OUTVOL + yb * OUTP + x * OUTE + z;
    float* ov = ou + 48 * OUTVOL;

#pragma unroll 2
    for (int yy = 0; yy < YCHUNK; yy++) {
        // ---- front-batched loads (18 x LDG.64) ----
        float2 qu4  = LD2(p, 4 * PLANE);
        float2 qv4  = LD2(p, 4 * PLANE + SLICE_C);
        float2 uzl  = LD2(p, 2 * PLANE - 2);
        float2 uzr  = LD2(p, 2 * PLANE + 2);
        float2 vzl  = LD2(p, 2 * PLANE - 2 + SLICE_C);
        float2 vzr  = LD2(p, 2 * PLANE + 2 + SLICE_C);
        float2 uxm1 = LD2(p, 2 * PLANE - ROW);
        float2 uxp1 = LD2(p, 2 * PLANE + ROW);
        float2 uxm2 = LD2(p, 2 * PLANE - 2 * ROW);
        float2 uxp2 = LD2(p, 2 * PLANE + 2 * ROW);
        float2 vxm1 = LD2(p, 2 * PLANE - ROW + SLICE_C);
        float2 vxp1 = LD2(p, 2 * PLANE + ROW + SLICE_C);
        float2 vxm2 = LD2(p, 2 * PLANE - 2 * ROW + SLICE_C);
        float2 vxp2 = LD2(p, 2 * PLANE + 2 * ROW + SLICE_C);
        float2 unx  = LD2(p, 2 * PLANE + STRIDE_T);
        float2 vnx  = LD2(p, 2 * PLANE + STRIDE_T + SLICE_C);

        qu[4] = qu4;
        qv[4] = qv4;

        float2 uc = qu[2];
        float2 vc = qv[2];

        // ---- u laplacian ----
        // point 0 (input z+2): z±1 = uzl.y, uc.y ; z±2 = uzl.x, uzr.x
        float s1u0 = uzl.y + uc.y + uxm1.x + uxp1.x + qu[1].x + qu[3].x;
        float s2u0 = uzl.x + uzr.x + uxm2.x + uxp2.x + qu[0].x + qu[4].x;
        // point 1 (input z+3): z±1 = uc.x, uzr.x ; z±2 = uzl.y, uzr.y
        float s1u1 = uc.x + uzr.x + uxm1.y + uxp1.y + qu[1].y + qu[3].y;
        float s2u1 = uzl.y + uzr.y + uxm2.y + uxp2.y + qu[0].y + qu[4].y;
        float lapu0 = (S1 * s1u0 + S0 * s2u0 + SC * uc.x) * INV_DX2;
        float lapu1 = (S1 * s1u1 + S0 * s2u1 + SC * uc.y) * INV_DX2;

        // ---- v laplacian ----
        float s1v0 = vzl.y + vc.y + vxm1.x + vxp1.x + qv[1].x + qv[3].x;
        float s2v0 = vzl.x + vzr.x + vxm2.x + vxp2.x + qv[0].x + qv[4].x;
        float s1v1 = vc.x + vzr.x + vxm1.y + vxp1.y + qv[1].y + qv[3].y;
        float s2v1 = vzl.y + vzr.y + vxm2.y + vxp2.y + qv[0].y + qv[4].y;
        float lapv0 = (S1 * s1v0 + S0 * s2v0 + SC * vc.x) * INV_DX2;
        float lapv1 = (S1 * s1v1 + S0 * s2v1 + SC * vc.y) * INV_DX2;

        // ---- reaction + time derivative ----
        float uvv0 = uc.x * vc.x * vc.x;
        float uvv1 = uc.y * vc.y * vc.y;
        float ut0 = (unx.x - uc.x) * INV_DT;
        float ut1 = (unx.y - uc.y) * INV_DT;
        float vt0 = (vnx.x - vc.x) * INV_DT;
        float vt1 = (vnx.y - vc.y) * INV_DT;

        float2 fu, fv;
        fu.x = DU * lapu0 - uvv0 + FF * (1.0f - uc.x) - ut0;
        fu.y = DU * lapu1 - uvv1 + FF * (1.0f - uc.y) - ut1;
        fv.x = DV * lapv0 + uvv0 - (FF + KK) * vc.x - vt0;
        fv.y = DV * lapv1 + uvv1 - (FF + KK) * vc.y - vt1;

        *(float2*)ou = fu;
        *(float2*)ov = fv;
        ou += OUTP;
        ov += OUTP;
        p  += PLANE;

        // shift queues
        qu[0] = qu[1]; qu[1] = qu[2]; qu[2] = qu[3]; qu[3] = qu[4];
        qv[0] = qv[1]; qv[1] = qv[2]; qv[2] = qv[3]; qv[3] = qv[4];
    }
}

extern "C" void kernel_launch(void* const* d_in, const int* in_sizes, int n_in,
                              void* d_out, int out_size)
{
    const float* in = (const float*)d_in[0];
    float* out = (float*)d_out;
    dim3 grid(24, 4, 48);    // x-tiles (96/4), y-chunks, t
    dim3 block(48, 4);       // z-pairs, x within tile
    gs_residual_v6<<<grid, block>>>(in, out);
}